// round 5
// baseline (speedup 1.0000x reference)
#include <cuda_runtime.h>

// QuantumSelfAttention: softmax(z,-1).mean(-1) == 1/4 exactly for every sample
// (softmax rows sum to 1; mean over that axis = 1/4). The entire quantum
// circuit is dead code w.r.t. the output. Output = 0.25 everywhere.
//
// out_size = 524288 floats (2 MiB, L2-resident). Kernel is launch-floor bound:
// ~0.2us of store work inside a ~3.9us kernel; DRAM 0%, issue ~10%.
// Frontier probe: 256 CTAs x 512 threads, one STG.128 per thread, exact cover.

__global__ void __launch_bounds__(512, 1)
qsa_fill_exact_kernel(float4* __restrict__ out4) {
    out4[blockIdx.x * 512 + threadIdx.x] =
        make_float4(0.25f, 0.25f, 0.25f, 0.25f);
}

// General fallbacks (not launched for this problem's out_size; kept for safety).
__global__ void qsa_fill_stride_kernel(float4* __restrict__ out4, int n4) {
    const float4 v = make_float4(0.25f, 0.25f, 0.25f, 0.25f);
    int idx = blockIdx.x * blockDim.x + threadIdx.x;
    int stride = gridDim.x * blockDim.x;
    for (int i = idx; i < n4; i += stride) out4[i] = v;
}
__global__ void qsa_fill_tail_kernel(float* __restrict__ out, int start, int n) {
    int i = start + blockIdx.x * blockDim.x + threadIdx.x;
    if (i < n) out[i] = 0.25f;
}

extern "C" void kernel_launch(void* const* d_in, const int* in_sizes, int n_in,
                              void* d_out, int out_size) {
    (void)d_in; (void)in_sizes; (void)n_in;

    float* out = (float*)d_out;
    int n4 = out_size >> 2;

    if ((out_size & 3) == 0 && (n4 & 511) == 0) {
        // Exact cover: one float4 per thread, 512 threads/block.
        // out_size=524288 -> n4=131072 -> 256 blocks.
        qsa_fill_exact_kernel<<<n4 / 512, 512>>>((float4*)out);
    } else {
        if (n4 > 0) {
            int blocks = (n4 + 255) / 256;
            if (blocks > 16384) blocks = 16384;
            qsa_fill_stride_kernel<<<blocks, 256>>>((float4*)out, n4);
        }
        int tail_start = n4 << 2;
        if (tail_start < out_size) {
            int rem = out_size - tail_start;
            qsa_fill_tail_kernel<<<(rem + 255) / 256, 256>>>(out, tail_start, out_size);
        }
    }
}

// round 6
// speedup vs baseline: 1.1646x; 1.1646x over previous
#include <cuda_runtime.h>

// QuantumSelfAttention: softmax(z,-1).mean(-1) == 1/4 exactly for every sample
// (softmax rows sum to 1; mean over that axis = 1/4). The entire quantum
// circuit is dead code w.r.t. the output. Output = 0.25 everywhere.
//
// out_size = 524288 floats (2 MiB, L2-resident). Kernel is launch-floor bound:
// ~0.2us of store work inside a ~3.9us kernel (DRAM 0%, L2 ~5%, issue ~10%).
// Shape frontier exhausted over R1-R5; best total measured at 128 CTAs x 1024
// threads, one STG.128 per thread, exact cover. This is the locked-in config.

__global__ void __launch_bounds__(1024, 1)
qsa_fill_exact_kernel(float4* __restrict__ out4) {
    out4[blockIdx.x * 1024 + threadIdx.x] =
        make_float4(0.25f, 0.25f, 0.25f, 0.25f);
}

// General fallbacks (not launched for this problem's out_size; kept for safety).
__global__ void qsa_fill_stride_kernel(float4* __restrict__ out4, int n4) {
    const float4 v = make_float4(0.25f, 0.25f, 0.25f, 0.25f);
    int idx = blockIdx.x * blockDim.x + threadIdx.x;
    int stride = gridDim.x * blockDim.x;
    for (int i = idx; i < n4; i += stride) out4[i] = v;
}
__global__ void qsa_fill_tail_kernel(float* __restrict__ out, int start, int n) {
    int i = start + blockIdx.x * blockDim.x + threadIdx.x;
    if (i < n) out[i] = 0.25f;
}

extern "C" void kernel_launch(void* const* d_in, const int* in_sizes, int n_in,
                              void* d_out, int out_size) {
    (void)d_in; (void)in_sizes; (void)n_in;

    float* out = (float*)d_out;
    int n4 = out_size >> 2;

    if ((out_size & 3) == 0 && (n4 & 1023) == 0) {
        // Exact cover: one float4 per thread, 1024 threads/block.
        // out_size=524288 -> n4=131072 -> 128 blocks.
        qsa_fill_exact_kernel<<<n4 / 1024, 1024>>>((float4*)out);
    } else {
        if (n4 > 0) {
            int blocks = (n4 + 255) / 256;
            if (blocks > 16384) blocks = 16384;
            qsa_fill_stride_kernel<<<blocks, 256>>>((float4*)out, n4);
        }
        int tail_start = n4 << 2;
        if (tail_start < out_size) {
            int rem = out_size - tail_start;
            qsa_fill_tail_kernel<<<(rem + 255) / 256, 256>>>(out, tail_start, out_size);
        }
    }
}